// round 3
// baseline (speedup 1.0000x reference)
#include <cuda_runtime.h>
#include <math.h>

// ---------------- problem constants (from setup_inputs) ----------------
#define D      256          // feature dim
#define K2     512          // concat [u|v] contraction dim
#define BRANCH 4
#define LEVELS 9
#define MAX_PAR 16384       // 4^7 = largest parent level

// ---------------- device scratch (no cudaMalloc allowed) ----------------
__device__ float g_uv[(size_t)MAX_PAR * K2];        // 32 MB: combined [u|v] per parent
__device__ float g_h[2][(size_t)MAX_PAR * D];       // 2x16 MB: ping-pong hidden states
__device__ float g_WcT[(size_t)K2 * D];             // 512 KB: WcT[k][i] = [Wl|Wr][i][k]

// ---------------- pack W: WcT[k*256+i] ----------------------------------
__global__ void pack_w_kernel(const float* __restrict__ Wl,
                              const float* __restrict__ Wr) {
    int idx = blockIdx.x * blockDim.x + threadIdx.x;   // over 512*256
    int k = idx >> 8;
    int i = idx & 255;
    float v = (k < D) ? Wl[i * D + k] : Wr[i * D + (k - D)];
    g_WcT[idx] = v;
}

// ---------------- combine children into uv ------------------------------
// u = 1*h0 + (2/3)h1 + (1/3)h2 ; v = (1/3)h1 + (2/3)h2 + 1*h3
__global__ void combine_kernel(const float* __restrict__ hin, int n_par) {
    int idx = blockIdx.x * blockDim.x + threadIdx.x;
    if (idx >= n_par * K2) return;
    int p = idx >> 9;          // parent
    int k = idx & 511;         // 0..511
    int c = k & 255;           // feature column
    const float* base = hin + ((size_t)p << 2) * D + c;   // child 0, col c
    float r;
    const float C13 = 1.0f / 3.0f;
    const float C23 = 2.0f / 3.0f;
    if (k < D) {
        r = base[0] + C23 * base[D] + C13 * base[2 * D];
    } else {
        r = C13 * base[D] + C23 * base[2 * D] + base[3 * D];
    }
    g_uv[idx] = r;
}

// ---------------- fused GEMM + bias + tanh ------------------------------
// hout[p][i] = tanh( sum_k uv[p][k] * WcT[k][i] + bias[p][i] )
// Block: 256 threads, tile = 32 parents x 256 outputs, K chunks of 32.
#define MT 32
__global__ void __launch_bounds__(256)
level_gemm_kernel(const float* __restrict__ bias,
                  float* __restrict__ hout, int n_par) {
    __shared__ float As[MT][32];      // uv tile
    __shared__ float Bs[32][D];       // WcT tile

    int tid = threadIdx.x;
    int tx = tid & 31;                // output column group
    int ty = tid >> 5;                // 0..7 -> 4 rows each
    int pbase = blockIdx.x * MT;

    float acc[4][8];
#pragma unroll
    for (int r = 0; r < 4; r++)
#pragma unroll
        for (int j = 0; j < 8; j++) acc[r][j] = 0.0f;

    for (int kk = 0; kk < K2; kk += 32) {
        // load A tile (32x32), 4 elems/thread, coalesced
#pragma unroll
        for (int i = 0; i < 4; i++) {
            int lin = tid + i * 256;
            int r = lin >> 5, c = lin & 31;
            int p = pbase + r;
            As[r][c] = (p < n_par) ? g_uv[(size_t)p * K2 + kk + c] : 0.0f;
        }
        // load B tile (32x256), 32 elems/thread, coalesced
#pragma unroll
        for (int i = 0; i < 32; i++) {
            int lin = tid + i * 256;
            int r = lin >> 8, c = lin & 255;
            Bs[r][c] = g_WcT[(size_t)(kk + r) * D + c];
        }
        __syncthreads();

#pragma unroll
        for (int k = 0; k < 32; k++) {
            float a0 = As[ty * 4 + 0][k];
            float a1 = As[ty * 4 + 1][k];
            float a2 = As[ty * 4 + 2][k];
            float a3 = As[ty * 4 + 3][k];
#pragma unroll
            for (int j = 0; j < 8; j++) {
                float b = Bs[k][tx + 32 * j];
                acc[0][j] += a0 * b;
                acc[1][j] += a1 * b;
                acc[2][j] += a2 * b;
                acc[3][j] += a3 * b;
            }
        }
        __syncthreads();
    }

    // epilogue: bias + tanh
#pragma unroll
    for (int r = 0; r < 4; r++) {
        int p = pbase + ty * 4 + r;
        if (p < n_par) {
#pragma unroll
            for (int j = 0; j < 8; j++) {
                int n = tx + 32 * j;
                float v = acc[r][j] + bias[(size_t)p * D + n];
                hout[(size_t)p * D + n] = tanhf(v);
            }
        }
    }
}

// ---------------- host launcher ------------------------------------------
extern "C" void kernel_launch(void* const* d_in, const int* in_sizes, int n_in,
                              void* d_out, int out_size) {
    const float* vectors = (const float*)d_in[0];
    const float* Wl      = (const float*)d_in[1];
    const float* Wr      = (const float*)d_in[2];
    float* out = (float*)d_out;

    // level offsets: offsets[l] = (4^l - 1)/3
    // l:      0  1  2   3   4    5     6     7      8
    int offsets[LEVELS];
    int s = 0, sz = 1;
    for (int l = 0; l < LEVELS; l++) { offsets[l] = s; s += sz; sz *= BRANCH; }

    float* hbuf;
    cudaGetSymbolAddress((void**)&hbuf, g_h);
    float* hb0 = hbuf;
    float* hb1 = hbuf + (size_t)MAX_PAR * D;

    // pack [Wl|Wr]^T once (L2-resident for all 8 level GEMMs)
    pack_w_kernel<<<(K2 * D) / 256, 256>>>(Wl, Wr);

    // initial h = leaf level = vectors[offsets[8] : ]
    const float* hin = vectors + (size_t)offsets[LEVELS - 1] * D;

    int n_par = 1 << (2 * (LEVELS - 2));   // 4^7 = 16384
    for (int l = LEVELS - 2; l >= 0; l--) {
        // 1) combine children -> g_uv
        int total = n_par * K2;
        combine_kernel<<<(total + 255) / 256, 256>>>(hin, n_par);

        // 2) GEMM + bias + tanh
        float* hout = (l == 0) ? out : ((l & 1) ? hb1 : hb0);
        const float* bias = vectors + (size_t)offsets[l] * D;
        int grid = (n_par + MT - 1) / MT;
        level_gemm_kernel<<<grid, 256>>>(bias, hout, n_par);

        hin = hout;
        n_par >>= 2;
    }
}

// round 6
// speedup vs baseline: 1.4279x; 1.4279x over previous
#include <cuda_runtime.h>
#include <math.h>

// ---------------- problem constants (from setup_inputs) ----------------
#define D       256          // feature dim
#define K2      512          // concat [u|v] contraction dim
#define LEVELS  9
#define MAX_PAR 16384        // 4^7 = largest parent level

// ---------------- device scratch (no cudaMalloc allowed) ----------------
__device__ float g_h[2][(size_t)MAX_PAR * D];   // ping-pong hidden states
__device__ float g_WcT[(size_t)K2 * D];         // WcT[k][i] = [Wl|Wr][i][k], 512 KB, L2-resident

// ---------------- packed f32x2 helpers ----------------------------------
#define FMA2(d, a, b, c) \
    asm("fma.rn.f32x2 %0, %1, %2, %3;" : "=l"(d) : "l"(a), "l"(b), "l"(c))

__device__ __forceinline__ unsigned long long pack2(float x) {
    unsigned long long r;
    unsigned xi = __float_as_uint(x);
    asm("mov.b64 %0, {%1, %1};" : "=l"(r) : "r"(xi));
    return r;
}

// ---------------- pack W: WcT[k*256+i] ----------------------------------
__global__ void pack_w_kernel(const float* __restrict__ Wl,
                              const float* __restrict__ Wr) {
    int idx = blockIdx.x * blockDim.x + threadIdx.x;   // over 512*256
    int k = idx >> 8;
    int i = idx & 255;
    g_WcT[idx] = (k < D) ? Wl[i * D + k] : Wr[i * D + (k - D)];
}

// ---------------- big-level fused combine+GEMM+bias+tanh ----------------
// Tile: 64 parents x 128 outputs per block, grid = (n_par/64, 2).
// A tile (uv) is computed on the fly from the 4 children rows.
// u = h0 + (2/3)h1 + (1/3)h2 ; v = (1/3)h1 + (2/3)h2 + h3
__global__ void __launch_bounds__(256)
gemm_big_kernel(const float* __restrict__ hin, const float* __restrict__ bias,
                float* __restrict__ hout) {
    __shared__ __align__(16) float As[32][66];    // [k][row], pad 66 keeps ull loads 8B-aligned
    __shared__ __align__(16) float Bs[32][128];

    const int tid = threadIdx.x;
    const int tx = tid & 31;          // column within 32-group
    const int ty = tid >> 5;          // 0..7 -> owns rows ty*8 .. ty*8+7
    const int pbase = blockIdx.x * 64;
    const int ncol0 = blockIdx.y * 128;

    const float C13 = 1.0f / 3.0f;
    const float C23 = 2.0f / 3.0f;

    unsigned long long acc[4][4];     // [row-pair][col j]; packed {row2rp, row2rp+1}
#pragma unroll
    for (int rp = 0; rp < 4; rp++)
#pragma unroll
        for (int j = 0; j < 4; j++) acc[rp][j] = 0ull;

    for (int kk = 0; kk < K2; kk += 32) {
        const bool is_u = (kk < D);
        const int kc = is_u ? kk : (kk - D);
        // A tile: 64 rows x 32 k -> 8 elems/thread, coalesced child reads
#pragma unroll
        for (int i = 0; i < 8; i++) {
            int lin = tid + i * 256;
            int r = lin >> 5;
            int c = lin & 31;
            const float* cb = hin + ((size_t)(pbase + r) * 4) * D + kc + c;
            float v;
            if (is_u) v = cb[0] + C23 * cb[D] + C13 * cb[2 * D];
            else      v = C13 * cb[D] + C23 * cb[2 * D] + cb[3 * D];
            As[c][r] = v;
        }
        // B tile: 32 k x 128 cols -> 16 elems/thread, coalesced
#pragma unroll
        for (int i = 0; i < 16; i++) {
            int lin = tid + i * 256;
            int r = lin >> 7;
            int c = lin & 127;
            Bs[r][c] = g_WcT[(size_t)(kk + r) * D + ncol0 + c];
        }
        __syncthreads();

#pragma unroll
        for (int k = 0; k < 32; k++) {
            unsigned long long av[4];
#pragma unroll
            for (int rp = 0; rp < 4; rp++)
                av[rp] = *reinterpret_cast<const unsigned long long*>(
                    &As[k][ty * 8 + 2 * rp]);                 // LDS.64, broadcast in warp
#pragma unroll
            for (int j = 0; j < 4; j++) {
                unsigned long long b2 = pack2(Bs[k][tx + 32 * j]);
#pragma unroll
                for (int rp = 0; rp < 4; rp++)
                    FMA2(acc[rp][j], av[rp], b2, acc[rp][j]);
            }
        }
        __syncthreads();
    }

    // epilogue: bias + tanh (acc pairs are two parent ROWS, same column)
#pragma unroll
    for (int rp = 0; rp < 4; rp++) {
        int p0 = pbase + ty * 8 + 2 * rp;
#pragma unroll
        for (int j = 0; j < 4; j++) {
            int n = ncol0 + tx + 32 * j;
            union { unsigned long long u; float2 f; } cv;
            cv.u = acc[rp][j];
            hout[(size_t)p0 * D + n] =
                tanhf(cv.f.x + bias[(size_t)p0 * D + n]);
            hout[(size_t)(p0 + 1) * D + n] =
                tanhf(cv.f.y + bias[(size_t)(p0 + 1) * D + n]);
        }
    }
}

// ---------------- small-level fused kernel ------------------------------
// 4 parents x full 256 outputs per block, grid = ceil(n_par/4).
// uv built cooperatively in smem, then each thread owns 2 column-pairs.
__global__ void __launch_bounds__(256)
gemm_small_kernel(const float* __restrict__ hin, const float* __restrict__ bias,
                  float* __restrict__ hout, int n_par) {
    __shared__ __align__(16) float uv_s[4][K2];

    const int tid = threadIdx.x;
    const int pbase = blockIdx.x * 4;
    const float C13 = 1.0f / 3.0f;
    const float C23 = 2.0f / 3.0f;

    // build uv for up to 4 parents: 2048 elems / 256 threads
#pragma unroll
    for (int i = 0; i < 8; i++) {
        int idx = tid + i * 256;
        int lp = idx >> 9;
        int k = idx & 511;
        int c = k & 255;
        int p = pbase + lp;
        float v = 0.0f;
        if (p < n_par) {
            const float* cb = hin + ((size_t)p * 4) * D + c;
            if (k < D) v = cb[0] + C23 * cb[D] + C13 * cb[2 * D];
            else       v = C13 * cb[D] + C23 * cb[2 * D] + cb[3 * D];
        }
        uv_s[lp][k] = v;
    }
    __syncthreads();

    const int lp = tid >> 6;          // parent within block
    const int cp = tid & 63;          // col-pair group
    const int p = pbase + lp;
    if (p >= n_par) return;
    const int n0 = 2 * cp;            // pairs {n0,n0+1} and {n0+128,n0+129}

    const float* wp = g_WcT + n0;
    unsigned long long acc0 = 0ull, acc1 = 0ull;
#pragma unroll 8
    for (int k = 0; k < K2; k++) {
        unsigned long long a2 = pack2(uv_s[lp][k]);
        unsigned long long b0 = *reinterpret_cast<const unsigned long long*>(
            wp + (size_t)k * D);
        unsigned long long b1 = *reinterpret_cast<const unsigned long long*>(
            wp + (size_t)k * D + 128);
        FMA2(acc0, a2, b0, acc0);
        FMA2(acc1, a2, b1, acc1);
    }

    union { unsigned long long u; float2 f; } c0, c1;
    c0.u = acc0; c1.u = acc1;
    float2 bv0 = *reinterpret_cast<const float2*>(&bias[(size_t)p * D + n0]);
    float2 bv1 = *reinterpret_cast<const float2*>(&bias[(size_t)p * D + n0 + 128]);
    float2 o0, o1;
    o0.x = tanhf(c0.f.x + bv0.x); o0.y = tanhf(c0.f.y + bv0.y);
    o1.x = tanhf(c1.f.x + bv1.x); o1.y = tanhf(c1.f.y + bv1.y);
    *reinterpret_cast<float2*>(&hout[(size_t)p * D + n0]) = o0;
    *reinterpret_cast<float2*>(&hout[(size_t)p * D + n0 + 128]) = o1;
}

// ---------------- host launcher ------------------------------------------
extern "C" void kernel_launch(void* const* d_in, const int* in_sizes, int n_in,
                              void* d_out, int out_size) {
    const float* vectors = (const float*)d_in[0];
    const float* Wl      = (const float*)d_in[1];
    const float* Wr      = (const float*)d_in[2];
    float* out = (float*)d_out;

    // level offsets: offsets[l] = (4^l - 1)/3
    int offsets[LEVELS];
    int s = 0, sz = 1;
    for (int l = 0; l < LEVELS; l++) { offsets[l] = s; s += sz; sz *= 4; }

    float* hbuf;
    cudaGetSymbolAddress((void**)&hbuf, g_h);
    float* hb0 = hbuf;
    float* hb1 = hbuf + (size_t)MAX_PAR * D;

    pack_w_kernel<<<(K2 * D) / 256, 256>>>(Wl, Wr);

    const float* hin = vectors + (size_t)offsets[LEVELS - 1] * D;
    int n_par = 1 << (2 * (LEVELS - 2));   // 16384

    for (int l = LEVELS - 2; l >= 0; l--) {
        float* hout = (l == 0) ? out : ((l & 1) ? hb1 : hb0);
        const float* bias = vectors + (size_t)offsets[l] * D;
        if (n_par >= 4096) {
            dim3 grid(n_par / 64, 2);
            gemm_big_kernel<<<grid, 256>>>(hin, bias, hout);
        } else {
            dim3 grid((n_par + 3) / 4, 1);
            gemm_small_kernel<<<grid, 256>>>(hin, bias, hout, n_par);
        }
        hin = hout;
        n_par >>= 2;
    }
}

// round 7
// speedup vs baseline: 2.4738x; 1.7324x over previous
#include <cuda_runtime.h>
#include <math.h>

// ---------------- problem constants (from setup_inputs) ----------------
#define D       256          // feature dim
#define K2      512          // concat [u|v] contraction dim
#define LEVELS  9
#define MAX_PAR 16384        // 4^7 = largest parent level

// ---------------- device scratch (no cudaMalloc allowed) ----------------
__device__ float g_h[2][(size_t)MAX_PAR * D];   // ping-pong hidden states
__device__ float g_WcT[(size_t)K2 * D];         // WcT[k][i] = [Wl|Wr][i][k], 512 KB, L2-resident

// ---------------- packed f32x2 helpers ----------------------------------
#define FMA2(d, a, b, c) \
    asm("fma.rn.f32x2 %0, %1, %2, %3;" : "=l"(d) : "l"(a), "l"(b), "l"(c))

__device__ __forceinline__ unsigned long long pack2(float x) {
    unsigned long long r;
    unsigned xi = __float_as_uint(x);
    asm("mov.b64 %0, {%1, %1};" : "=l"(r) : "r"(xi));
    return r;
}

// ---------------- pack W via smem tile transpose -------------------------
// WcT[k][i] = Wl[i][k] (k<256) / Wr[i][k-256]. Coalesced both directions.
__global__ void __launch_bounds__(256)
pack_w_kernel(const float* __restrict__ Wl, const float* __restrict__ Wr) {
    __shared__ float t[32][33];
    const float* src = blockIdx.z ? Wr : Wl;
    int i0 = blockIdx.x * 32;                 // source row block (i)
    int k0 = blockIdx.y * 32;                 // source col block (k)
    int lx = threadIdx.x, ly = threadIdx.y;   // 32 x 8
#pragma unroll
    for (int r = 0; r < 4; r++)
        t[ly + 8 * r][lx] = src[(size_t)(i0 + ly + 8 * r) * D + k0 + lx];
    __syncthreads();
#pragma unroll
    for (int r = 0; r < 4; r++) {
        int k = k0 + ly + 8 * r + (blockIdx.z ? D : 0);
        g_WcT[(size_t)k * D + i0 + lx] = t[lx][ly + 8 * r];
    }
}

// ---------------- big-level fused combine+GEMM+bias+tanh ----------------
// Tile: 64 parents x 128 outputs per block, grid = (n_par/64, 2).
// u = h0 + (2/3)h1 + (1/3)h2 ; v = (1/3)h1 + (2/3)h2 + h3
__global__ void __launch_bounds__(256)
gemm_big_kernel(const float* __restrict__ hin, const float* __restrict__ bias,
                float* __restrict__ hout) {
    __shared__ __align__(16) float As[32][66];    // [k][row], pad keeps ull loads 8B-aligned
    __shared__ __align__(16) float Bs[32][128];

    const int tid = threadIdx.x;
    const int tx = tid & 31;
    const int ty = tid >> 5;
    const int pbase = blockIdx.x * 64;
    const int ncol0 = blockIdx.y * 128;

    const float C13 = 1.0f / 3.0f;
    const float C23 = 2.0f / 3.0f;

    unsigned long long acc[4][4];
#pragma unroll
    for (int rp = 0; rp < 4; rp++)
#pragma unroll
        for (int j = 0; j < 4; j++) acc[rp][j] = 0ull;

    for (int kk = 0; kk < K2; kk += 32) {
        const bool is_u = (kk < D);
        const int kc = is_u ? kk : (kk - D);
#pragma unroll
        for (int i = 0; i < 8; i++) {
            int lin = tid + i * 256;
            int r = lin >> 5;
            int c = lin & 31;
            const float* cb = hin + ((size_t)(pbase + r) * 4) * D + kc + c;
            float v;
            if (is_u) v = cb[0] + C23 * cb[D] + C13 * cb[2 * D];
            else      v = C13 * cb[D] + C23 * cb[2 * D] + cb[3 * D];
            As[c][r] = v;
        }
#pragma unroll
        for (int i = 0; i < 16; i++) {
            int lin = tid + i * 256;
            int r = lin >> 7;
            int c = lin & 127;
            Bs[r][c] = g_WcT[(size_t)(kk + r) * D + ncol0 + c];
        }
        __syncthreads();

#pragma unroll
        for (int k = 0; k < 32; k++) {
            unsigned long long av[4];
#pragma unroll
            for (int rp = 0; rp < 4; rp++)
                av[rp] = *reinterpret_cast<const unsigned long long*>(
                    &As[k][ty * 8 + 2 * rp]);
#pragma unroll
            for (int j = 0; j < 4; j++) {
                unsigned long long b2 = pack2(Bs[k][tx + 32 * j]);
#pragma unroll
                for (int rp = 0; rp < 4; rp++)
                    FMA2(acc[rp][j], av[rp], b2, acc[rp][j]);
            }
        }
        __syncthreads();
    }

#pragma unroll
    for (int rp = 0; rp < 4; rp++) {
        int p0 = pbase + ty * 8 + 2 * rp;
#pragma unroll
        for (int j = 0; j < 4; j++) {
            int n = ncol0 + tx + 32 * j;
            union { unsigned long long u; float2 f; } cv;
            cv.u = acc[rp][j];
            hout[(size_t)p0 * D + n] =
                tanhf(cv.f.x + bias[(size_t)p0 * D + n]);
            hout[(size_t)(p0 + 1) * D + n] =
                tanhf(cv.f.y + bias[(size_t)(p0 + 1) * D + n]);
        }
    }
}

// ---------------- small-level kernel: K-split across warps ---------------
// Block: 8 parents x 32 cols; K2=512 split 8 warps x 64 k.
// Grid: (ceil(n_par/8), 8 col-groups). Partials reduced via smem.
#define PT 8
__global__ void __launch_bounds__(256)
gemm_small_kernel(const float* __restrict__ hin, const float* __restrict__ bias,
                  float* __restrict__ hout, int n_par) {
    __shared__ float uv_s[PT][K2];        // 16 KB
    __shared__ float part[8][PT][32];     // 8 KB

    const int tid = threadIdx.x;
    const int pbase = blockIdx.x * PT;
    const int col0 = blockIdx.y * 32;
    const float C13 = 1.0f / 3.0f;
    const float C23 = 2.0f / 3.0f;

    // build uv for up to 8 parents: 4096 elems / 256 threads
#pragma unroll
    for (int i = 0; i < PT * K2 / 256; i++) {
        int idx = tid + i * 256;
        int lp = idx >> 9;
        int k = idx & 511;
        int c = k & 255;
        int p = pbase + lp;
        float v = 0.0f;
        if (p < n_par) {
            const float* cb = hin + ((size_t)p * 4) * D + c;
            if (k < D) v = cb[0] + C23 * cb[D] + C13 * cb[2 * D];
            else       v = C13 * cb[D] + C23 * cb[2 * D] + cb[3 * D];
        }
        uv_s[lp][k] = v;
    }
    __syncthreads();

    const int w = tid >> 5;               // k-segment 0..7
    const int lane = tid & 31;
    const float* wp = g_WcT + (size_t)(w * 64) * D + col0 + lane;

    float acc[PT];
#pragma unroll
    for (int p = 0; p < PT; p++) acc[p] = 0.0f;

#pragma unroll 8
    for (int k = 0; k < 64; k++) {
        float wv = wp[(size_t)k * D];     // coalesced 128B per warp
        int kg = w * 64 + k;
#pragma unroll
        for (int p = 0; p < PT; p++)
            acc[p] = fmaf(uv_s[p][kg], wv, acc[p]);   // smem broadcast
    }
#pragma unroll
    for (int p = 0; p < PT; p++) part[w][p][lane] = acc[p];
    __syncthreads();

    // reduce 8 k-segments: tid -> (parent, lane)
    int p = tid >> 5;
    int pg = pbase + p;
    if (pg < n_par) {
        float s = 0.0f;
#pragma unroll
        for (int w2 = 0; w2 < 8; w2++) s += part[w2][p][lane];
        int n = col0 + lane;
        hout[(size_t)pg * D + n] = tanhf(s + bias[(size_t)pg * D + n]);
    }
}

// ---------------- host launcher ------------------------------------------
extern "C" void kernel_launch(void* const* d_in, const int* in_sizes, int n_in,
                              void* d_out, int out_size) {
    const float* vectors = (const float*)d_in[0];
    const float* Wl      = (const float*)d_in[1];
    const float* Wr      = (const float*)d_in[2];
    float* out = (float*)d_out;

    int offsets[LEVELS];
    int s = 0, sz = 1;
    for (int l = 0; l < LEVELS; l++) { offsets[l] = s; s += sz; sz *= 4; }

    float* hbuf;
    cudaGetSymbolAddress((void**)&hbuf, g_h);
    float* hb0 = hbuf;
    float* hb1 = hbuf + (size_t)MAX_PAR * D;

    pack_w_kernel<<<dim3(8, 8, 2), dim3(32, 8)>>>(Wl, Wr);

    const float* hin = vectors + (size_t)offsets[LEVELS - 1] * D;
    int n_par = 1 << (2 * (LEVELS - 2));   // 16384

    for (int l = LEVELS - 2; l >= 0; l--) {
        float* hout = (l == 0) ? out : ((l & 1) ? hb1 : hb0);
        const float* bias = vectors + (size_t)offsets[l] * D;
        if (n_par >= 4096) {
            dim3 grid(n_par / 64, 2);
            gemm_big_kernel<<<grid, 256>>>(hin, bias, hout);
        } else {
            dim3 grid((n_par + PT - 1) / PT, 8);
            gemm_small_kernel<<<grid, 256>>>(hin, bias, hout, n_par);
        }
        hin = hout;
        n_par >>= 2;
    }
}